// round 14
// baseline (speedup 1.0000x reference)
#include <cuda_runtime.h>
#include <cuda_bf16.h>
#include <math.h>
#include <stdint.h>

#define B_ 64
#define L_ 512
#define E_ 512
#define C_ 32
#define U_ 8
#define K_ 9
#define S_ 256

// ---------------- scratch (device globals; no allocation) ----------------
__device__ float g_h[(size_t)B_ * L_ * C_];            // 4 MB   conv1 output [B,L,C]
__device__ float g_p[(size_t)B_ * U_ * S_ * C_];       // 16 MB  squashed primary caps
__device__ __nv_bfloat16 g_w2[8 * 288 * 64];           // conv1 W2 bf16, [chunk][n=t*32+co][k]
__device__ float g_wp[U_ * 288 * 32];                  // Wpack fp32, [u][n=kk*32+d][c] (= W^T per (u,k))
__device__ float g_pwT[C_ * 9 * U_ * C_];              // prim weights transposed [ci][t][uc]
__device__ float g_logA[B_ * U_ * K_];
__device__ float g_logB[B_ * U_ * K_];

__device__ __forceinline__ uint32_t smem_u32(const void* p) {
    uint32_t a;
    asm("{ .reg .u64 t; cvta.to.shared.u64 t, %1; cvt.u32.u64 %0, t; }" : "=r"(a) : "l"(p));
    return a;
}
__device__ __forceinline__ uint32_t f2tf32(float f) {
    uint32_t r;
    asm("cvt.rna.tf32.f32 %0, %1;" : "=r"(r) : "f"(f));
    return r;
}
#define MMA_TF32(acc, a, b0, b1)                                              \
    asm volatile(                                                             \
        "mma.sync.aligned.m16n8k8.row.col.f32.tf32.tf32.f32 "                 \
        "{%0,%1,%2,%3}, {%4,%5,%6,%7}, {%8,%9}, {%0,%1,%2,%3};"               \
        : "+f"((acc)[0]), "+f"((acc)[1]), "+f"((acc)[2]), "+f"((acc)[3])      \
        : "r"((a)[0]), "r"((a)[1]), "r"((a)[2]), "r"((a)[3]),                 \
          "r"(b0), "r"(b1))

// ---------------- weight prep: conv W2 (bf16), Wpack (fp32), prim transpose ----------
__global__ void k_prep(const float* __restrict__ c1w, const float* __restrict__ pw,
                       const float* __restrict__ W) {
    int i = blockIdx.x * 256 + threadIdx.x;
    if (i < 288 * 512) {
        int n = i >> 9, e = i & 511;
        int t = n >> 5, co = n & 31;
        float val = c1w[(co * 512 + e) * 9 + t];
        g_w2[(size_t)(e >> 6) * 288 * 64 + n * 64 + (e & 63)] = __float2bfloat16(val);
        return;
    }
    int j = i - 288 * 512;
    if (j < C_ * 9 * 256) {
        int ci = j / (9 * 256), t = (j / 256) % 9, uc = j % 256;
        g_pwT[j] = pw[(uc * C_ + ci) * 9 + t];
        return;
    }
    int m = j - C_ * 9 * 256;
    if (m < U_ * 288 * 32) {
        int u = m / 9216, rem = m % 9216;
        int n = rem >> 5, c = rem & 31;
        int kk = n >> 5, d = n & 31;
        g_wp[(size_t)(u * 288 + n) * 32 + c] = W[(size_t)(((u * 9 + kk) * 32 + c)) * 32 + d];
    }
}

// ---------------- conv1 via mma.sync (bf16 HMMA): Y = X @ W2^T, 9-tap epilogue -------
__global__ void __launch_bounds__(256) k_conv1_mma(const int* __restrict__ x,
                                                   const float* __restrict__ mask,
                                                   const float* __restrict__ emb,
                                                   const float* __restrict__ bias) {
    extern __shared__ char cvsm[];
    __nv_bfloat16* As = (__nv_bfloat16*)cvsm;             // [128][72]
    __nv_bfloat16* Bs = (__nv_bfloat16*)(cvsm + 18432);   // [288][72]
    float* Ysm = (float*)(cvsm + 59904);                  // [128][292]
    int*   tsm = (int*)(cvsm + 209408);
    float* msm = (float*)(cvsm + 209920);
    float* bsm = (float*)(cvsm + 210432);

    int tid = threadIdx.x, lane = tid & 31, w = tid >> 5;
    int wm = w >> 2, wn = w & 3;
    int cx = blockIdx.x, b = blockIdx.y;
    int lorg = cx * 120 - 4;

    if (tid < 128) {
        int l = lorg + tid;
        if (l >= 0 && l < L_) { tsm[tid] = x[b * L_ + l]; msm[tid] = mask[b * L_ + l]; }
        else                  { tsm[tid] = -1;            msm[tid] = 0.f; }
    }
    if (tid < 32) bsm[tid] = bias[tid];

    float acc[4][9][4];
#pragma unroll
    for (int mt = 0; mt < 4; mt++)
#pragma unroll
        for (int nt = 0; nt < 9; nt++)
#pragma unroll
            for (int j = 0; j < 4; j++) acc[mt][nt][j] = 0.f;

    uint32_t As32 = smem_u32(As), Bs32 = smem_u32(Bs);
    int rowA = wm * 64 + (((lane >> 3) & 1) << 3) + (lane & 7);
    int colA = ((lane >> 4) & 1) << 3;
    uint32_t aBase = As32 + (uint32_t)(rowA * 72 + colA) * 2;
    int rowB = wn * 72 + (lane & 7);
    int colB = ((lane >> 3) & 1) << 3;
    uint32_t bBase = Bs32 + (uint32_t)(rowB * 72 + colB) * 2;

    const float4* emb4 = (const float4*)emb;
    const uint4* w2g = (const uint4*)g_w2;

#pragma unroll 1
    for (int kc = 0; kc < 8; kc++) {
        __syncthreads();
        for (int i = tid; i < 2048; i += 256) {
            int r = i >> 4, q = i & 15;
            int tok = tsm[r];
            float4 v = make_float4(0.f, 0.f, 0.f, 0.f);
            if (tok >= 0) {
                v = emb4[(size_t)tok * 128 + kc * 16 + q];
                float m = msm[r];
                v.x *= m; v.y *= m; v.z *= m; v.w *= m;
            }
            __nv_bfloat162 h0 = __floats2bfloat162_rn(v.x, v.y);
            __nv_bfloat162 h1 = __floats2bfloat162_rn(v.z, v.w);
            uint2 pk = make_uint2(*(unsigned*)&h0, *(unsigned*)&h1);
            *(uint2*)((char*)As + r * 144 + q * 8) = pk;
        }
        for (int i = tid; i < 2304; i += 256) {
            uint4 v = w2g[kc * 2304 + i];
            int n = i >> 3, seg = i & 7;
            *(uint4*)((char*)Bs + n * 144 + seg * 16) = v;
        }
        __syncthreads();
#pragma unroll
        for (int ks = 0; ks < 4; ks++) {
            uint32_t bf[9][2];
#pragma unroll
            for (int nt = 0; nt < 9; nt++) {
                uint32_t addr = bBase + (uint32_t)(nt * 576 + ks * 16) * 2;
                asm volatile("ldmatrix.sync.aligned.m8n8.x2.shared.b16 {%0,%1}, [%2];"
                             : "=r"(bf[nt][0]), "=r"(bf[nt][1]) : "r"(addr));
            }
#pragma unroll
            for (int mt = 0; mt < 4; mt++) {
                uint32_t af[4];
                uint32_t addr = aBase + (uint32_t)(mt * 1152 + ks * 16) * 2;
                asm volatile("ldmatrix.sync.aligned.m8n8.x4.shared.b16 {%0,%1,%2,%3}, [%4];"
                             : "=r"(af[0]), "=r"(af[1]), "=r"(af[2]), "=r"(af[3]) : "r"(addr));
#pragma unroll
                for (int nt = 0; nt < 9; nt++) {
                    asm volatile(
                        "mma.sync.aligned.m16n8k16.row.col.f32.bf16.bf16.f32 "
                        "{%0,%1,%2,%3}, {%4,%5,%6,%7}, {%8,%9}, {%0,%1,%2,%3};"
                        : "+f"(acc[mt][nt][0]), "+f"(acc[mt][nt][1]),
                          "+f"(acc[mt][nt][2]), "+f"(acc[mt][nt][3])
                        : "r"(af[0]), "r"(af[1]), "r"(af[2]), "r"(af[3]),
                          "r"(bf[nt][0]), "r"(bf[nt][1]));
                }
            }
        }
    }
    __syncthreads();

    int r0 = wm * 64 + (lane >> 2);
    int c0 = wn * 72 + ((lane & 3) << 1);
#pragma unroll
    for (int mt = 0; mt < 4; mt++) {
#pragma unroll
        for (int nt = 0; nt < 9; nt++) {
            int r = r0 + mt * 16, c = c0 + nt * 8;
            *(float2*)(Ysm + r * 292 + c)       = make_float2(acc[mt][nt][0], acc[mt][nt][1]);
            *(float2*)(Ysm + (r + 8) * 292 + c) = make_float2(acc[mt][nt][2], acc[mt][nt][3]);
        }
    }
    __syncthreads();

    for (int i = tid; i < 120 * 32; i += 256) {
        int j = i >> 5, co = i & 31;
        float v = bsm[co];
#pragma unroll
        for (int t = 0; t < 9; t++) v += Ysm[(j + t) * 292 + t * 32 + co];
        int l = cx * 120 + j;
        if (l < L_) g_h[((size_t)(b * L_ + l)) * C_ + co] = fmaxf(v, 0.f);
    }
}

// ---------------- primary caps conv: 32 -> 256, k=9, pad 4, stride 2, + squash -------
__global__ void __launch_bounds__(256) k_prim(const float* __restrict__ bias) {
    __shared__ float sbuf[9504];
    int b = blockIdx.y;
    int sb = blockIdx.x * 32;
    int tid = threadIdx.x;
    int ucg = tid >> 3, sg = tid & 7;
    float acc[8][4];
#pragma unroll
    for (int i = 0; i < 8; i++)
#pragma unroll
        for (int j = 0; j < 4; j++) acc[i][j] = 0.f;

    float* hsm = sbuf;
    float* wsm = sbuf + 288;
    int lorg = 2 * sb - 4;

    for (int ch = 0; ch < 8; ch++) {
        int ci0 = ch * 4;
        __syncthreads();
        for (int row = tid; row < 72; row += 256) {
            int l = lorg + row;
            float4 v = make_float4(0.f, 0.f, 0.f, 0.f);
            if (l >= 0 && l < L_)
                v = *(const float4*)(g_h + ((size_t)(b * L_ + l)) * C_ + ci0);
            hsm[row] = v.x;
            hsm[72 + row] = v.y;
            hsm[144 + row] = v.z;
            hsm[216 + row] = v.w;
        }
        {
            const float4* src = (const float4*)(g_pwT + ci0 * 2304);
            float4* dst = (float4*)wsm;
            for (int idx = tid; idx < 2304; idx += 256) dst[idx] = src[idx];
        }
        __syncthreads();
#pragma unroll
        for (int cl = 0; cl < 4; cl++) {
            float hv[16];
            const float4* hr = (const float4*)(hsm + cl * 72 + sg * 8);
#pragma unroll
            for (int q = 0; q < 4; q++) {
                float4 v = hr[q];
                hv[q * 4 + 0] = v.x; hv[q * 4 + 1] = v.y;
                hv[q * 4 + 2] = v.z; hv[q * 4 + 3] = v.w;
            }
#pragma unroll
            for (int t = 0; t < 9; t++) {
                const float* wp = wsm + (cl * 9 + t) * 256 + ucg * 8;
                float4 wa = *(const float4*)wp;
                float4 wb = *(const float4*)(wp + 4);
                float wv[8] = {wa.x, wa.y, wa.z, wa.w, wb.x, wb.y, wb.z, wb.w};
#pragma unroll
                for (int j = 0; j < 4; j++) {
                    float h = hv[2 * j + t];
#pragma unroll
                    for (int i = 0; i < 8; i++) acc[i][j] = fmaf(wv[i], h, acc[i][j]);
                }
            }
        }
    }
    __syncthreads();
    float* psm = sbuf;
    float bi[8];
#pragma unroll
    for (int i = 0; i < 8; i++) bi[i] = bias[ucg * 8 + i];
#pragma unroll
    for (int j = 0; j < 4; j++)
#pragma unroll
        for (int i = 0; i < 8; i++)
            psm[(sg * 4 + j) * 257 + ucg * 8 + i] = acc[i][j] + bi[i];
    __syncthreads();
    int u = tid >> 5, sl = tid & 31;
    const float* pr = psm + sl * 257 + u * 32;
    float sq = 0.f;
#pragma unroll
    for (int c = 0; c < 32; c++) { float pv = pr[c]; sq += pv * pv; }
    float sc = (sq / (1.f + sq)) * rsqrtf(sq + 1e-8f);
    float* dst = g_p + (((size_t)(b * U_ + u)) * S_ + sb + sl) * C_;
#pragma unroll
    for (int c = 0; c < 32; c++) dst[c] = pr[c] * sc;
}

// ---------------- fused routing (NO u_hat materialization) -------------------------
// Grid (K,B), 256 threads (8 warps; warp w owns s-rows [32w,32w+32)).
// Pass 1: s_vec[s,d] = sum_u c_u * (p_u @ W_uk^T-as-stored) via tf32 mma.
// Squash in registers (quad shfl). v -> Vsm.
// Pass 2 (PHASE<2): per u, partial M = p_u^T @ v over this warp's 32 s-rows,
//   agree partial = <W_uk, M>, warp+block reduce -> logits.
// PHASE 2: column-mean of Vsm -> out.
template <int PHASE>
__global__ void __launch_bounds__(256) k_route_f(float* __restrict__ out) {
    extern __shared__ float rsm[];
    float* Pm  = rsm;               // [256][36]
    float* Wk  = rsm + 9216;        // [8][32][33]
    float* Vsm = Wk + 8448;         // [256][33]
    float* agg = Vsm + 8448;        // [8][8]
    __shared__ float cs[8];
    int k = blockIdx.x, b = blockIdx.y;
    int tid = threadIdx.x, lane = tid & 31, w = tid >> 5;
    int gid = lane >> 2, tig = lane & 3;

    if (PHASE == 0) {
        if (tid < 8) cs[tid] = 1.f / 9.f;
    } else {
        const float* lin = (PHASE == 1) ? g_logA : g_logB;
        if (tid < 8) {
            const float* lp = lin + (b * U_ + tid) * K_;
            float lg[9], m = -1e30f;
#pragma unroll
            for (int i = 0; i < 9; i++) { lg[i] = lp[i]; m = fmaxf(m, lg[i]); }
            float sum = 0.f;
#pragma unroll
            for (int i = 0; i < 9; i++) sum += expf(lg[i] - m);
            cs[tid] = expf(lg[k] - m) / sum;
        }
    }
    // stage Wk[u][d][c] (stride 33) = W[u,k,c,d]
    for (int i = tid; i < 2048; i += 256) {
        int u = i >> 8, d = (i >> 3) & 31, c4 = i & 7;
        float4 v = ((const float4*)g_wp)[(u * 288 + k * 32 + d) * 8 + c4];
        float* dst = Wk + (u * 32 + d) * 33 + c4 * 4;
        dst[0] = v.x; dst[1] = v.y; dst[2] = v.z; dst[3] = v.w;
    }

    // ---- pass 1: s_vec ----
    float acc[2][4][4];
#pragma unroll
    for (int mt = 0; mt < 2; mt++)
#pragma unroll
        for (int nt = 0; nt < 4; nt++)
#pragma unroll
            for (int j = 0; j < 4; j++) acc[mt][nt][j] = 0.f;

#pragma unroll 1
    for (int u = 0; u < 8; u++) {
        __syncthreads();   // Wk/cs ready (u=0) or prior frag loads done
        const float4* p4 = (const float4*)(g_p + ((size_t)(b * U_ + u)) * S_ * C_);
        for (int i = tid; i < 2048; i += 256) {
            float4 v = p4[i];
            float* d = Pm + (i >> 3) * 36 + (i & 7) * 4;
            d[0] = v.x; d[1] = v.y; d[2] = v.z; d[3] = v.w;
        }
        __syncthreads();
        float cu = cs[u];
#pragma unroll
        for (int ks = 0; ks < 4; ks++) {
            uint32_t af[2][4];
#pragma unroll
            for (int mt = 0; mt < 2; mt++) {
                const float* ar = Pm + (w * 32 + mt * 16 + gid) * 36 + ks * 8 + tig;
                af[mt][0] = f2tf32(ar[0]);
                af[mt][1] = f2tf32(ar[288]);
                af[mt][2] = f2tf32(ar[4]);
                af[mt][3] = f2tf32(ar[292]);
            }
#pragma unroll
            for (int nt = 0; nt < 4; nt++) {
                const float* br = Wk + (u * 32 + nt * 8 + gid) * 33 + ks * 8 + tig;
                uint32_t b0 = f2tf32(cu * br[0]);
                uint32_t b1 = f2tf32(cu * br[4]);
#pragma unroll
                for (int mt = 0; mt < 2; mt++) MMA_TF32(acc[mt][nt], af[mt], b0, b1);
            }
        }
    }

    // ---- squash (warp-local rows) + write v to Vsm ----
#pragma unroll
    for (int mt = 0; mt < 2; mt++) {
#pragma unroll
        for (int h = 0; h < 2; h++) {
            float sq = 0.f;
#pragma unroll
            for (int nt = 0; nt < 4; nt++)
                sq += acc[mt][nt][2 * h] * acc[mt][nt][2 * h] +
                      acc[mt][nt][2 * h + 1] * acc[mt][nt][2 * h + 1];
            sq += __shfl_xor_sync(0xffffffffu, sq, 1);
            sq += __shfl_xor_sync(0xffffffffu, sq, 2);
            float sc = (sq / (1.f + sq)) * rsqrtf(sq + 1e-8f);
            int r = w * 32 + mt * 16 + gid + 8 * h;
#pragma unroll
            for (int nt = 0; nt < 4; nt++) {
                Vsm[r * 33 + nt * 8 + tig * 2]     = acc[mt][nt][2 * h] * sc;
                Vsm[r * 33 + nt * 8 + tig * 2 + 1] = acc[mt][nt][2 * h + 1] * sc;
            }
        }
    }

    if (PHASE < 2) {
        // ---- pass 2: agree via partial M = p_u^T @ v (per-warp s-slice) ----
        int s0 = w * 32;
#pragma unroll 1
        for (int u = 0; u < 8; u++) {
            __syncthreads();   // Vsm ready (u=0) / prior frag loads done
            const float4* p4 = (const float4*)(g_p + ((size_t)(b * U_ + u)) * S_ * C_);
            for (int i = tid; i < 2048; i += 256) {
                float4 v = p4[i];
                float* d = Pm + (i >> 3) * 36 + (i & 7) * 4;
                d[0] = v.x; d[1] = v.y; d[2] = v.z; d[3] = v.w;
            }
            __syncthreads();
            float macc[2][4][4];
#pragma unroll
            for (int mt = 0; mt < 2; mt++)
#pragma unroll
                for (int nt = 0; nt < 4; nt++)
#pragma unroll
                    for (int j = 0; j < 4; j++) macc[mt][nt][j] = 0.f;
#pragma unroll
            for (int ks = 0; ks < 4; ks++) {
                uint32_t af[2][4];
#pragma unroll
                for (int mt = 0; mt < 2; mt++) {
                    // A[m=c][k=s_local] = p[s0+k][c]
                    const float* ac = Pm + (s0 + ks * 8 + tig) * 36 + mt * 16 + gid;
                    af[mt][0] = f2tf32(ac[0]);
                    af[mt][1] = f2tf32(ac[8]);
                    af[mt][2] = f2tf32(ac[144]);   // +4 s rows
                    af[mt][3] = f2tf32(ac[152]);
                }
#pragma unroll
                for (int nt = 0; nt < 4; nt++) {
                    // B[n=d][k=s_local] = v[s0+k][d]
                    const float* bc = Vsm + (s0 + ks * 8 + tig) * 33 + nt * 8 + gid;
                    uint32_t b0 = f2tf32(bc[0]);
                    uint32_t b1 = f2tf32(bc[132]); // +4 s rows
#pragma unroll
                    for (int mt = 0; mt < 2; mt++) MMA_TF32(macc[mt][nt], af[mt], b0, b1);
                }
            }
            // agree partial = <W_uk, M>
            float part = 0.f;
#pragma unroll
            for (int mt = 0; mt < 2; mt++)
#pragma unroll
                for (int nt = 0; nt < 4; nt++)
#pragma unroll
                    for (int j = 0; j < 4; j++) {
                        int c = mt * 16 + gid + ((j >> 1) << 3);
                        int d = nt * 8 + tig * 2 + (j & 1);
                        part += macc[mt][nt][j] * Wk[(u * 32 + d) * 33 + c];
                    }
#pragma unroll
            for (int off = 16; off > 0; off >>= 1)
                part += __shfl_xor_sync(0xffffffffu, part, off);
            if (lane == 0) agg[u * 8 + w] = part;
        }
        __syncthreads();
        if (tid < 8) {
            float t = 0.f;
#pragma unroll
            for (int ww = 0; ww < 8; ww++) t += agg[tid * 8 + ww];
            int li = (b * U_ + tid) * K_ + k;
            if (PHASE == 0) g_logA[li] = t;
            else            g_logB[li] = g_logA[li] + t;
        }
    } else {
        // ---- mean over s -> out ----
        __syncthreads();   // Vsm complete
        int col = tid & 31, seg = tid >> 5;
        float t = 0.f;
#pragma unroll
        for (int r = 0; r < 32; r++) t += Vsm[(seg * 32 + r) * 33 + col];
        Pm[seg * 32 + col] = t;
        __syncthreads();
        if (tid < 32) {
            float a = 0.f;
#pragma unroll
            for (int g = 0; g < 8; g++) a += Pm[g * 32 + tid];
            out[(b * K_ + k) * C_ + tid] = a * (1.f / 256.f);
        }
    }
}

// ---------------- launch ----------------
extern "C" void kernel_launch(void* const* d_in, const int* in_sizes, int n_in,
                              void* d_out, int out_size) {
    const int*   x    = (const int*)d_in[0];
    const float* mask = (const float*)d_in[1];
    const float* emb  = (const float*)d_in[2];
    const float* c1w  = (const float*)d_in[3];
    const float* c1b  = (const float*)d_in[4];
    const float* pw   = (const float*)d_in[5];
    const float* pb   = (const float*)d_in[6];
    const float* W    = (const float*)d_in[7];
    float* out = (float*)d_out;

    const int CONV_SMEM  = 210560;
    const int ROUTE_SMEM = (9216 + 8448 + 8448 + 64) * 4;  // 104704
    static int attr_set = 0;
    if (!attr_set) {
        cudaFuncSetAttribute(k_conv1_mma, cudaFuncAttributeMaxDynamicSharedMemorySize, CONV_SMEM);
        cudaFuncSetAttribute(k_route_f<0>, cudaFuncAttributeMaxDynamicSharedMemorySize, ROUTE_SMEM);
        cudaFuncSetAttribute(k_route_f<1>, cudaFuncAttributeMaxDynamicSharedMemorySize, ROUTE_SMEM);
        cudaFuncSetAttribute(k_route_f<2>, cudaFuncAttributeMaxDynamicSharedMemorySize, ROUTE_SMEM);
        attr_set = 1;
    }

    int prep_elems = 288 * 512 + C_ * 9 * 256 + U_ * 288 * 32;
    k_prep<<<(prep_elems + 255) / 256, 256>>>(c1w, pw, W);
    k_conv1_mma<<<dim3(5, B_), 256, CONV_SMEM>>>(x, mask, emb, c1b);
    k_prim<<<dim3(S_ / 32, B_), 256>>>(pb);
    k_route_f<0><<<dim3(K_, B_), 256, ROUTE_SMEM>>>(out);
    k_route_f<1><<<dim3(K_, B_), 256, ROUTE_SMEM>>>(out);
    k_route_f<2><<<dim3(K_, B_), 256, ROUTE_SMEM>>>(out);
}